// round 17
// baseline (speedup 1.0000x reference)
#include <cuda_runtime.h>
#include <cuda_fp16.h>

// ---------------------------------------------------------------------------
// FrameLevelPartFeatureExtractor — FP16 tensor-core (mma.sync m16n8k16) conv
// pipeline. Intermediates fp16 cpair-interleaved [N][C/2][H][W][2].
// R17: conv2/3/4 at 4 blocks/SM (launch_bounds(256,4)); weights streamed
// per-chunk inside the 2-stage buffer (uniform 45.5KB smem). conv1 im2col
// MMA (+folded weight pack). conv5/6 ONEROW M=64 unchanged.
// Final conv6 writes fp32 NCHW.
// ---------------------------------------------------------------------------

typedef unsigned int uint;
typedef unsigned long long u64;

__device__ __align__(16) uint g_bufA[8388608];
__device__ __align__(16) uint g_bufB[8388608];
__device__ __align__(16) uint g_bufW[69120];   // packed fp16 weights, w2..w6

__device__ __forceinline__ float dlrelu(float v) {
    return v > 0.0f ? v : 0.01f * (0.01f * v);
}
__device__ __forceinline__ uint pack_h2(float lo, float hi) {
    uint r; asm("cvt.rn.f16x2.f32 %0, %1, %2;" : "=r"(r) : "f"(hi), "f"(lo));
    return r;
}
__device__ __forceinline__ uint max_h2(uint a, uint b) {
    uint r; asm("max.f16x2 %0, %1, %2;" : "=r"(r) : "r"(a), "r"(b));
    return r;
}
__device__ __forceinline__ void cp16(unsigned dst, const void* src, int sz) {
    asm volatile("cp.async.cg.shared.global [%0], [%1], 16, %2;\n"
                 :: "r"(dst), "l"(src), "r"(sz));
}
__device__ __forceinline__ void cp4(unsigned dst, const void* src, int sz) {
    asm volatile("cp.async.ca.shared.global [%0], [%1], 4, %2;\n"
                 :: "r"(dst), "l"(src), "r"(sz));
}
__device__ __forceinline__ void cp_commit() {
    asm volatile("cp.async.commit_group;\n" ::);
}
__device__ __forceinline__ void mma_f16(float* c, uint a0, uint a1, uint a2,
                                        uint a3, uint b0, uint b1) {
    asm volatile(
        "mma.sync.aligned.m16n8k16.row.col.f32.f16.f16.f32 "
        "{%0,%1,%2,%3}, {%4,%5,%6,%7}, {%8,%9}, {%0,%1,%2,%3};"
        : "+f"(c[0]), "+f"(c[1]), "+f"(c[2]), "+f"(c[3])
        : "r"(a0), "r"(a1), "r"(a2), "r"(a3), "r"(b0), "r"(b1));
}

// ---------------------------------------------------------------------------
// conv1 via im2col MMA: 5x5, Cin=1, Cout=32, K = 25 taps padded to 32.
// Block 8h x 64w x 32oc; warp = one h row, M=64 x N=32.
// First 270 blocks also pack the fp16 weights for layers 2..6.
// ---------------------------------------------------------------------------
__global__ __launch_bounds__(256, 2)
void conv1_mma(const float* __restrict__ in, const float* __restrict__ w1,
               uint* __restrict__ out,
               const float* __restrict__ w2, const float* __restrict__ w3,
               const float* __restrict__ w4, const float* __restrict__ w5,
               const float* __restrict__ w6, uint* __restrict__ pk)
{
    extern __shared__ __align__(16) uint arena1[];
    float* sfl = (float*)arena1;            //   832 words: fp32 tile [12][68]
    uint*  A_s = arena1 + 832;              // 10240 words: im2col A
    uint*  B_s = arena1 + 832 + 10240;      //   512 words: packed B

    const int H = 1024, W = 256;
    const int n  = blockIdx.z;
    const int h0 = blockIdx.y * 8;
    const int w0 = blockIdx.x * 64;
    const int tid  = threadIdx.x;
    const int lane = tid & 31;
    const int wid  = tid >> 5;
    const int g2 = lane >> 2, g4 = lane & 3;

    const int ss = (h0 >> 9) << 9;          // sliceH = 512
    for (int i = tid; i < 816; i += 256) {
        int r = i / 68, c = i - r * 68;
        int g = h0 - 2 + r, gc = w0 - 2 + c;
        float v = 0.0f;
        if (g >= ss && g < ss + 512 && gc >= 0 && gc < W)
            v = in[((size_t)n * H + g) * W + gc];
        sfl[r * 68 + c] = v;
    }

    {
        int kc = tid >> 7, nn = (tid >> 5) & 3, ln = tid & 31;
        int oc = nn * 8 + (ln >> 2);
        int kb = kc * 16 + 2 * (ln & 3);
        float f0 = (kb     < 25) ? w1[oc * 25 + kb]     : 0.0f;
        float f1 = (kb + 1 < 25) ? w1[oc * 25 + kb + 1] : 0.0f;
        float f2 = (kb + 8 < 25) ? w1[oc * 25 + kb + 8] : 0.0f;
        float f3 = (kb + 9 < 25) ? w1[oc * 25 + kb + 9] : 0.0f;
        B_s[((kc * 4 + nn) * 32 + ln) * 2]     = pack_h2(f0, f1);
        B_s[((kc * 4 + nn) * 32 + ln) * 2 + 1] = pack_h2(f2, f3);
    }
    __syncthreads();

    for (int it = 0; it < 32; it++) {
        int i = tid + it * 256;
        int j = i & 15;
        int w = (i >> 4) & 63;
        int h = i >> 10;
        int k0 = 2 * j, k1 = k0 + 1;
        float v0 = 0.0f, v1 = 0.0f;
        if (k0 < 25) v0 = sfl[(h + k0 / 5) * 68 + (w + k0 % 5)];
        if (k1 < 25) v1 = sfl[(h + k1 / 5) * 68 + (w + k1 % 5)];
        A_s[(h * 64 + w) * 20 + j] = pack_h2(v0, v1);
    }
    __syncthreads();

    float acc[4][4][4];
#pragma unroll
    for (int m = 0; m < 4; m++)
#pragma unroll
        for (int nn = 0; nn < 4; nn++)
#pragma unroll
            for (int x = 0; x < 4; x++) acc[m][nn][x] = 0.0f;

    const int abase = (wid * 64 + g2) * 20 + g4;
#pragma unroll
    for (int kc = 0; kc < 2; kc++) {
        uint b[4][2];
#pragma unroll
        for (int nn = 0; nn < 4; nn++) {
            uint2 v = reinterpret_cast<const uint2*>(B_s)[(kc * 4 + nn) * 32 + lane];
            b[nn][0] = v.x;
            b[nn][1] = v.y;
        }
#pragma unroll
        for (int m = 0; m < 4; m++) {
            int ai = abase + m * 320 + kc * 8;
            uint a0 = A_s[ai];
            uint a1 = A_s[ai + 160];
            uint a2 = A_s[ai + 4];
            uint a3 = A_s[ai + 164];
#pragma unroll
            for (int nn = 0; nn < 4; nn++)
                mma_f16(acc[m][nn], a0, a1, a2, a3, b[nn][0], b[nn][1]);
        }
    }

    const int h = h0 + wid;
#pragma unroll
    for (int m = 0; m < 4; m++) {
#pragma unroll
        for (int nn = 0; nn < 4; nn++) {
            int ocp = nn * 4 + g4;
            int wv  = w0 + m * 16 + g2;
            uint* p = out + (((size_t)n * 16 + ocp) * H + h) * W + wv;
            p[0] = pack_h2(dlrelu(acc[m][nn][0]), dlrelu(acc[m][nn][1]));
            p[8] = pack_h2(dlrelu(acc[m][nn][2]), dlrelu(acc[m][nn][3]));
        }
    }

    // ---- folded weight pack for layers 2..6 (blocks 0..269) ----
    {
        int bid = (blockIdx.z * gridDim.y + blockIdx.y) * gridDim.x + blockIdx.x;
        if (bid < 270) {
            int idx = bid * 256 + tid;
            const float* w; int CIN, NCH, TAPS_, local;
            if (idx < 4608)       { w = w2; CIN = 32;  NCH = 2; TAPS_ = 9; local = idx; }
            else if (idx < 13824) { w = w3; CIN = 32;  NCH = 2; TAPS_ = 9; local = idx - 4608; }
            else if (idx < 32256) { w = w4; CIN = 64;  NCH = 4; TAPS_ = 9; local = idx - 13824; }
            else if (idx < 44544) { w = w5; CIN = 64;  NCH = 4; TAPS_ = 3; local = idx - 32256; }
            else                  { w = w6; CIN = 128; NCH = 8; TAPS_ = 3; local = idx - 44544; }
            int j    = local & 1;
            int r1   = local >> 1;
            int ln   = r1 & 31;
            int r2   = r1 >> 5;
            int nn   = r2 & 3;
            int r3   = r2 >> 2;
            int tap  = r3 % TAPS_;
            int r4   = r3 / TAPS_;
            int t    = r4 % NCH;
            int ocg  = r4 / NCH;
            int oc   = ocg * 32 + nn * 8 + (ln >> 2);
            int cin  = t * 16 + 2 * ((ln & 3) + 4 * j);
            int tapIdx = (TAPS_ == 3) ? (tap + 3) : tap;
            float v0 = w[(oc * CIN + cin) * 9 + tapIdx];
            float v1 = w[(oc * CIN + cin + 1) * 9 + tapIdx];
            pk[idx] = pack_h2(v0, v1);
        }
    }
}

// ---------------------------------------------------------------------------
// Non-ONEROW 3x3 conv (conv2/3/4): M=32 warp tile, 2-stage pipeline with
// weights STREAMED per chunk inside the stage buffer (uniform 45.5KB smem),
// 4 blocks/SM. Block tile 8h x 32w x 32oc.
// POOL: fused 2x2 maxpool epilogue (stash aliases dead arena).
// ---------------------------------------------------------------------------
template <int CIN, int POOL>
__global__ __launch_bounds__(256, 4)
void conv3x3_s2(const uint* __restrict__ in, const uint* __restrict__ pk,
                void* __restrict__ outv, int H, int W, int sliceH, int OCG)
{
    constexpr int TH    = 8;
    constexpr int ROWS  = TH + 2;
    constexpr int PLANE = 424;
    constexpr int SI_W  = 8 * PLANE;            // 3392 words
    constexpr int CHUNK_W = 9 * 256;            // 2304 words of weights/chunk
    constexpr int STG_W = SI_W + CHUNK_W;       // 5696 words per stage
    constexpr int NCH   = CIN / 16;
    constexpr int NROWOPS = 8 * ROWS * 10;      // 9 cp16 + 1 cp4 per row
    constexpr int NI    = (NROWOPS + 255) / 256;
    constexpr int NWOPS = 9 * 64;               // 576 cp16 per chunk
    constexpr int ARENA = 2 * STG_W;            // 11392 words = 45568B

    static_assert(!POOL || ARENA >= TH * 32 * 18, "pool stash fits");
    static_assert(NCH >= 2, "pipeline needs >= 2 chunks");

    extern __shared__ __align__(16) uint arena[];
    uint* sO = arena;

    const int z    = blockIdx.z;
    const int ocg  = z % OCG;
    const int n    = z / OCG;
    const int h0   = blockIdx.y * TH;
    const int w0   = blockIdx.x * 32;
    const int tid  = threadIdx.x;
    const int lane = tid & 31;
    const int wid  = tid >> 5;
    const int g2 = lane >> 2;
    const int g4 = lane & 3;

    const int ss = (h0 / sliceH) * sliceH;
    const int se = ss + sliceH;

    const int C2in = CIN / 2;
    const uint* base = in + (size_t)n * C2in * H * W;
    const uint* pk0  = pk + (size_t)(ocg * NCH) * CHUNK_W;

    int di_dst[NI], di_off[NI];
#pragma unroll
    for (int k = 0; k < NI; k++) {
        int i = tid + k * 256;
        int dst = -1, off = -1;
        if (i < NROWOPS) {
            int rowid = i / 10, sub = i - rowid * 10;
            int c = rowid / ROWS, r = rowid - c * ROWS;
            int g = h0 - 1 + r;
            bool rowok = (g >= ss && g < se);
            int word = c * PLANE + r * 40 + sub * 4;
            if (sub < 9) {
                int gc = w0 - 4 + sub * 4;
                dst = (word * 4) | 1;
                off = (rowok && gc >= 0) ? ((c * H + g) * W + gc) : -1;
            } else {
                int gc = w0 + 32;
                dst = word * 4;
                off = (rowok && gc < W) ? ((c * H + g) * W + gc) : -1;
            }
        }
        di_dst[k] = dst; di_off[k] = off;
    }

    unsigned ar_s = (unsigned)__cvta_generic_to_shared(arena);

    auto stage = [&](int t, int buf) {
        const uint* cb = base + (size_t)t * 8 * H * W;
        unsigned sd = ar_s + (unsigned)buf * (STG_W * 4);
#pragma unroll
        for (int k = 0; k < NI; k++) {
            int d = di_dst[k];
            if (d >= 0) {
                int off = di_off[k];
                if (d & 1)
                    cp16(sd + (unsigned)(d ^ 1),
                         off >= 0 ? (const void*)(cb + off) : (const void*)cb,
                         off >= 0 ? 16 : 0);
                else
                    cp4(sd + (unsigned)d,
                        off >= 0 ? (const void*)(cb + off) : (const void*)cb,
                        off >= 0 ? 4 : 0);
            }
        }
        const uint* wb = pk0 + (size_t)t * CHUNK_W;
        unsigned wd = sd + SI_W * 4;
#pragma unroll
        for (int k = 0; k < 3; k++) {
            int i = tid + k * 256;
            if (i < NWOPS)
                cp16(wd + (unsigned)i * 16, wb + i * 4, 16);
        }
        cp_commit();
    };

    stage(0, 0);

    float acc[2][4][4];
#pragma unroll
    for (int m = 0; m < 2; m++)
#pragma unroll
        for (int nn = 0; nn < 4; nn++)
#pragma unroll
            for (int x = 0; x < 4; x++) acc[m][nn][x] = 0.0f;

    const int abase = g4 * PLANE + wid * 40 + g2 + 3;
    const int a2off = 4 * PLANE;

    for (int t = 0; t < NCH; t++) {
        asm volatile("cp.async.wait_group 0;\n" ::);
        __syncthreads();
        if (t + 1 < NCH) stage(t + 1, (t + 1) & 1);

        const uint* sif = arena + (t & 1) * STG_W;
        const uint* sbf = sif + SI_W;
#pragma unroll
        for (int r = 0; r < 3; r++) {
#pragma unroll
            for (int q = 0; q < 3; q++) {
                const int tap = r * 3 + q;
                uint b[4][2];
#pragma unroll
                for (int nn = 0; nn < 4; nn++) {
                    uint2 v = *reinterpret_cast<const uint2*>(
                        sbf + ((tap * 4 + nn) * 32 + lane) * 2);
                    b[nn][0] = v.x;
                    b[nn][1] = v.y;
                }
#pragma unroll
                for (int m = 0; m < 2; m++) {
                    int ai = abase + r * 40 + q + m * 16;
                    uint a0 = sif[ai];
                    uint a1 = sif[ai + 8];
                    uint a2 = sif[ai + a2off];
                    uint a3 = sif[ai + a2off + 8];
#pragma unroll
                    for (int nn = 0; nn < 4; nn++)
                        mma_f16(acc[m][nn], a0, a1, a2, a3,
                                b[nn][0], b[nn][1]);
                }
            }
        }
    }

    if (POOL) {
        __syncthreads();
#pragma unroll
        for (int m = 0; m < 2; m++)
#pragma unroll
            for (int nn = 0; nn < 4; nn++) {
                int ocp = nn * 4 + g4;
                int wl  = m * 16 + g2;
                sO[wid * (32 * 18) + wl * 18 + ocp] =
                    pack_h2(dlrelu(acc[m][nn][0]), dlrelu(acc[m][nn][1]));
                sO[wid * (32 * 18) + (wl + 8) * 18 + ocp] =
                    pack_h2(dlrelu(acc[m][nn][2]), dlrelu(acc[m][nn][3]));
            }
        __syncthreads();
        uint* out = (uint*)outv;
        const int C2out = OCG * 16;
        const int H2 = H >> 1, W2 = W >> 1;
        const int pw = tid & 15, ph = (tid >> 4) & 3, ob = tid >> 6;
#pragma unroll
        for (int k = 0; k < 4; k++) {
            int ocp = ob * 4 + k;
            const uint* s0 = sO + (2 * ph) * (32 * 18) + (2 * pw) * 18 + ocp;
            uint v = max_h2(max_h2(s0[0], s0[18]),
                            max_h2(s0[32 * 18], s0[32 * 18 + 18]));
            out[((size_t)(n * C2out + ocg * 16 + ocp) * H2 + (h0 >> 1) + ph) * W2
                + (w0 >> 1) + pw] = v;
        }
    } else {
        uint* out = (uint*)outv;
        const int C2out = OCG * 16;
        const int h = h0 + wid;
#pragma unroll
        for (int m = 0; m < 2; m++) {
#pragma unroll
            for (int nn = 0; nn < 4; nn++) {
                int ocp = ocg * 16 + nn * 4 + g4;
                int wv  = w0 + m * 16 + g2;
                uint* p = out + ((size_t)(n * C2out + ocp) * H + h) * W + wv;
                p[0] = pack_h2(dlrelu(acc[m][nn][0]), dlrelu(acc[m][nn][1]));
                p[8] = pack_h2(dlrelu(acc[m][nn][2]), dlrelu(acc[m][nn][3]));
            }
        }
    }
}

// ---------------------------------------------------------------------------
// ONEROW 1x3 conv (conv5/6): M=64 warp tile, 3-stage A pipeline, resident
// weights. Block tile 8h x 64w x 32oc; warp = one h row, M=64 x N=32.
// B fragments preloaded across all 3 taps. FINAL: fp32 NCHW output.
// ---------------------------------------------------------------------------
template <int CIN, int FINAL>
__global__ __launch_bounds__(256, 2)
void conv1x3_s3(const uint* __restrict__ in, const uint* __restrict__ pk,
                void* __restrict__ outv, int H, int W, int OCG)
{
    constexpr int TH    = 8;
    constexpr int ROWS  = TH;
    constexpr int PLANE = 584;
    constexpr int SI_W  = 8 * PLANE;
    constexpr int CHUNK_W = 3 * 256;
    constexpr int NCH   = CIN / 16;
    constexpr int NROWOPS = 8 * ROWS * 18;
    constexpr int NI    = (NROWOPS + 255) / 256;
    constexpr int NWT   = NCH * 3 * 64;
    constexpr int NW    = (NWT + 255) / 256;

    static_assert(NCH >= 2, "pipeline needs >= 2 chunks");

    extern __shared__ __align__(16) uint arena[];
    uint* si_p = arena;
    uint* sw_p = arena + 3 * SI_W;

    const int z    = blockIdx.z;
    const int ocg  = z % OCG;
    const int n    = z / OCG;
    const int h0   = blockIdx.y * TH;
    const int w0   = blockIdx.x * 64;
    const int tid  = threadIdx.x;
    const int lane = tid & 31;
    const int wid  = tid >> 5;
    const int g2 = lane >> 2;
    const int g4 = lane & 3;

    const int C2in = CIN / 2;
    const uint* base = in + (size_t)n * C2in * H * W;
    const uint* pk0  = pk + (size_t)(ocg * NCH) * CHUNK_W;

    int di_dst[NI], di_off[NI];
#pragma unroll
    for (int k = 0; k < NI; k++) {
        int i = tid + k * 256;
        int dst = -1, off = -1;
        if (i < NROWOPS) {
            int rowid = i / 18, sub = i - rowid * 18;
            int c = rowid / ROWS, r = rowid - c * ROWS;
            int g = h0 + r;
            int gc = w0 - 4 + sub * 4;
            dst = (c * PLANE + r * 72 + sub * 4) * 4;
            off = (gc >= 0 && gc < W) ? ((c * H + g) * W + gc) : -1;
        }
        di_dst[k] = dst; di_off[k] = off;
    }

    unsigned si_s = (unsigned)__cvta_generic_to_shared(si_p);
    unsigned sw_s = (unsigned)__cvta_generic_to_shared(sw_p);

    auto stageA = [&](int t, int buf) {
        const uint* cb = base + (size_t)t * 8 * H * W;
        unsigned sd = si_s + (unsigned)buf * (SI_W * 4);
#pragma unroll
        for (int k = 0; k < NI; k++) {
            int d = di_dst[k];
            if (d >= 0) {
                int off = di_off[k];
                cp16(sd + (unsigned)d,
                     off >= 0 ? (const void*)(cb + off) : (const void*)cb,
                     off >= 0 ? 16 : 0);
            }
        }
    };

#pragma unroll
    for (int k = 0; k < NW; k++) {
        int i = tid + k * 256;
        if (NWT % 256 == 0 || i < NWT)
            cp16(sw_s + (unsigned)i * 16, pk0 + i * 4, 16);
    }
    stageA(0, 0);
    cp_commit();
    stageA(1, 1);
    cp_commit();

    float acc[4][4][4];
#pragma unroll
    for (int m = 0; m < 4; m++)
#pragma unroll
        for (int nn = 0; nn < 4; nn++)
#pragma unroll
            for (int x = 0; x < 4; x++) acc[m][nn][x] = 0.0f;

    const int abase = g4 * PLANE + wid * 72 + g2 + 3;
    const int a2off = 4 * PLANE;

    for (int t = 0; t < NCH; t++) {
        if (t + 1 < NCH) asm volatile("cp.async.wait_group 1;\n" ::);
        else             asm volatile("cp.async.wait_group 0;\n" ::);
        __syncthreads();
        if (t + 2 < NCH) { stageA(t + 2, (t + 2) % 3); cp_commit(); }

        const uint* sif = si_p + (t % 3) * SI_W;
        const uint* sbf = sw_p + t * CHUNK_W;

        uint ball[3][4][2];
#pragma unroll
        for (int q = 0; q < 3; q++)
#pragma unroll
            for (int nn = 0; nn < 4; nn++) {
                uint2 v = *reinterpret_cast<const uint2*>(
                    sbf + ((q * 4 + nn) * 32 + lane) * 2);
                ball[q][nn][0] = v.x;
                ball[q][nn][1] = v.y;
            }
#pragma unroll
        for (int q = 0; q < 3; q++) {
#pragma unroll
            for (int m = 0; m < 4; m++) {
                int ai = abase + q + m * 16;
                uint a0 = sif[ai];
                uint a1 = sif[ai + 8];
                uint a2 = sif[ai + a2off];
                uint a3 = sif[ai + a2off + 8];
#pragma unroll
                for (int nn = 0; nn < 4; nn++)
                    mma_f16(acc[m][nn], a0, a1, a2, a3,
                            ball[q][nn][0], ball[q][nn][1]);
            }
        }
    }

    if (FINAL) {
        float* out = (float*)outv;
        const int Cout = OCG * 32;
        const int h = h0 + wid;
#pragma unroll
        for (int m = 0; m < 4; m++) {
#pragma unroll
            for (int nn = 0; nn < 4; nn++) {
                int oc = ocg * 32 + nn * 8 + 2 * g4;
                int wv = w0 + m * 16 + g2;
                float* p0 = out + ((size_t)(n * Cout + oc) * H + h) * W + wv;
                float* p1 = p0 + (size_t)H * W;
                p0[0] = dlrelu(acc[m][nn][0]);
                p1[0] = dlrelu(acc[m][nn][1]);
                p0[8] = dlrelu(acc[m][nn][2]);
                p1[8] = dlrelu(acc[m][nn][3]);
            }
        }
    } else {
        uint* out = (uint*)outv;
        const int C2out = OCG * 16;
        const int h = h0 + wid;
#pragma unroll
        for (int m = 0; m < 4; m++) {
#pragma unroll
            for (int nn = 0; nn < 4; nn++) {
                int ocp = ocg * 16 + nn * 4 + g4;
                int wv  = w0 + m * 16 + g2;
                uint* p = out + ((size_t)(n * C2out + ocp) * H + h) * W + wv;
                p[0] = pack_h2(dlrelu(acc[m][nn][0]), dlrelu(acc[m][nn][1]));
                p[8] = pack_h2(dlrelu(acc[m][nn][2]), dlrelu(acc[m][nn][3]));
            }
        }
    }
}

// ---------------------------------------------------------------------------
extern "C" void kernel_launch(void* const* d_in, const int* in_sizes, int n_in,
                              void* d_out, int out_size)
{
    const float* x  = (const float*)d_in[0];
    const float* w1 = (const float*)d_in[1];
    const float* w2 = (const float*)d_in[2];
    const float* w3 = (const float*)d_in[3];
    const float* w4 = (const float*)d_in[4];
    const float* w5 = (const float*)d_in[5];
    const float* w6 = (const float*)d_in[6];

    uint *A, *B, *Wp;
    cudaGetSymbolAddress((void**)&A, g_bufA);
    cudaGetSymbolAddress((void**)&B, g_bufB);
    cudaGetSymbolAddress((void**)&Wp, g_bufW);

    const int o2 = 0, o3 = 4608, o4 = 13824, o5 = 32256, o6 = 44544;

    // Dynamic smem sizes (bytes)
    const int SM_C1 = (832 + 10240 + 512) * 4;     // 46336 (conv1 im2col)
    const int SM_CX = 2 * (3392 + 2304) * 4;       // 45568 (conv2/3/4 uniform)
    const int SM_O5 = (3 * 4672 + 4 * 768) * 4;    // 68352 (CIN=64 ONEROW)
    const int SM_O6 = (3 * 4672 + 8 * 768) * 4;    // 80640 (CIN=128 ONEROW)

    cudaFuncSetAttribute(conv1_mma,
                         cudaFuncAttributeMaxDynamicSharedMemorySize, SM_C1);
    cudaFuncSetAttribute(conv3x3_s2<32, 1>,
                         cudaFuncAttributeMaxDynamicSharedMemorySize, SM_CX);
    cudaFuncSetAttribute(conv3x3_s2<32, 0>,
                         cudaFuncAttributeMaxDynamicSharedMemorySize, SM_CX);
    cudaFuncSetAttribute(conv3x3_s2<64, 1>,
                         cudaFuncAttributeMaxDynamicSharedMemorySize, SM_CX);
    cudaFuncSetAttribute(conv1x3_s3<64, 0>,
                         cudaFuncAttributeMaxDynamicSharedMemorySize, SM_O5);
    cudaFuncSetAttribute(conv1x3_s3<128, 1>,
                         cudaFuncAttributeMaxDynamicSharedMemorySize, SM_O6);

    // conv1 (im2col MMA, +folded weight pack): x -> A fp16 [2][16cp][1024][256]
    conv1_mma<<<dim3(4, 128, 2), 256, SM_C1>>>(x, w1, A, w2, w3, w4, w5, w6, Wp);

    // conv2 (+pool1 fused): A -> B fp16 [2][16cp][512][128]
    conv3x3_s2<32, 1><<<dim3(8, 128, 2), 256, SM_CX>>>(
        A, Wp + o2, B, 1024, 256, 512, 1);

    // conv3: B -> A fp16 [2][32cp][512][128] (sliceH=32)
    conv3x3_s2<32, 0><<<dim3(4, 64, 4), 256, SM_CX>>>(
        B, Wp + o3, A, 512, 128, 32, 2);

    // conv4 (+pool2 fused): A -> B fp16 [2][32cp][256][64]
    conv3x3_s2<64, 1><<<dim3(4, 64, 4), 256, SM_CX>>>(
        A, Wp + o4, B, 512, 128, 32, 2);

    // conv5: B -> A fp16 [2][64cp][256][64] (1x3 middle row)
    conv1x3_s3<64, 0><<<dim3(1, 32, 8), 256, SM_O5>>>(
        B, Wp + o5, A, 256, 64, 4);

    // conv6: A -> out fp32 NCHW [2,128,256,64] (final)
    conv1x3_s3<128, 1><<<dim3(1, 32, 8), 256, SM_O6>>>(
        A, Wp + o6, d_out, 256, 64, 4);
}